// round 2
// baseline (speedup 1.0000x reference)
#include <cuda_runtime.h>
#include <math.h>

// Problem constants (fixed by the dataset)
#define D      128
#define BT     32
#define LSEQ   256
#define NTOK   (BT*LSEQ)     // 8192
#define NHEAD  8
#define DK     16
#define DI     512
#define NMAX   100000
#define NLAYER 2

// ---------------- scratch (device globals; no allocation allowed) ----------------
__device__ float g_side[(size_t)NMAX * D];
__device__ float g_x[(size_t)NTOK * D];
__device__ float g_q[(size_t)NTOK * D];
__device__ float g_k[(size_t)NTOK * D];
__device__ float g_v[(size_t)NTOK * D];
__device__ float g_o[(size_t)NTOK * D];
__device__ float g_h[(size_t)NTOK * DI];

// ---------------- utility kernels ----------------
__global__ void zero_kernel(float* __restrict__ p, int n4) {
    int i = blockIdx.x * blockDim.x + threadIdx.x;
    if (i < n4) ((float4*)p)[i] = make_float4(0.f, 0.f, 0.f, 0.f);
}

// ---------------- sorted-COO SpMM with run-length accumulation ----------------
#define EPB 256
__global__ __launch_bounds__(D) void spmm_kernel(
    const float* __restrict__ vals, const int* __restrict__ rows,
    const int* __restrict__ cols, const float* __restrict__ ego,
    float* __restrict__ side, int nnz)
{
    __shared__ int   s_row[EPB];
    __shared__ int   s_col[EPB];
    __shared__ float s_val[EPB];
    int e0 = blockIdx.x * EPB;
    int cnt = min(EPB, nnz - e0);
    if (cnt <= 0) return;
    for (int i = threadIdx.x; i < cnt; i += blockDim.x) {
        s_row[i] = rows[e0 + i];
        s_col[i] = cols[e0 + i];
        s_val[i] = vals[e0 + i];
    }
    __syncthreads();
    int t = threadIdx.x;                 // dimension index 0..127
    float acc = 0.f;
    int cur = s_row[0];
    for (int i = 0; i < cnt; i++) {
        int r = s_row[i];
        if (r != cur) {
            atomicAdd(&side[(size_t)cur * D + t], acc);
            acc = 0.f;
            cur = r;
        }
        acc = fmaf(s_val[i], __ldg(&ego[(size_t)s_col[i] * D + t]), acc);
    }
    atomicAdd(&side[(size_t)cur * D + t], acc);
}

// ---------------- high-intensity fp32 GEMM, 128x128x8 tile, 8x8 microtile -------
// C[M,N] = epi(Aop[M,K] @ W[K,N]) where Aop is A (ASRC=0), A+A2 (1), A*A2 (2).
// Epilogue: +bias, +res (HASRES), activation (ACT: 0 none, 1 relu, 2 leaky 0.01),
// += C (ACCUM), fused LayerNorm over the 128 columns (LNFUSE; requires N==BN==128).
#define BM 128
#define BN 128
#define BK 8
#define PAD 4

template<int ASRC, int ACT, bool ACCUM, bool HASRES, bool LNFUSE>
__global__ __launch_bounds__(256, 2) void gemm_tpl(
    const float* __restrict__ A, const float* __restrict__ A2,
    const float* __restrict__ W, const float* __restrict__ bias,
    const float* __restrict__ res, const float* __restrict__ lng,
    const float* __restrict__ lnb, float* __restrict__ C,
    int M, int N, int K)
{
    __shared__ float As[2][BK][BM + PAD];
    __shared__ float Bs[2][BK][BN + PAD];

    int tid = threadIdx.x;
    int tx = tid & 15;
    int ty = tid >> 4;
    int row0 = blockIdx.y * BM;
    int col0 = blockIdx.x * BN;

    // A loader: thread -> (row ar, k-quad akc)
    int ar  = tid >> 1;                 // 0..127
    int akc = (tid & 1) * 4;            // 0 or 4
    int grow = row0 + ar;
    bool aval = grow < M;
    const float* Ap  = A + (size_t)grow * K + akc;
    const float* A2p = A2 ? (A2 + (size_t)grow * K + akc) : A;

    // B loader: thread -> (k-row bkr, col-quad bc4)
    int bkr = tid >> 5;                 // 0..7
    int bc4 = (tid & 31) * 4;           // 0..124
    const float* Wp = W + (size_t)bkr * N + col0 + bc4;

    float acc[8][8] = {};
    float4 av, bv;

    // prologue: tile 0
    if (aval) {
        float4 a = *(const float4*)Ap;
        if (ASRC == 0) av = a;
        else {
            float4 s = *(const float4*)A2p;
            if (ASRC == 1) av = make_float4(a.x+s.x, a.y+s.y, a.z+s.z, a.w+s.w);
            else           av = make_float4(a.x*s.x, a.y*s.y, a.z*s.z, a.w*s.w);
        }
    } else av = make_float4(0.f,0.f,0.f,0.f);
    bv = *(const float4*)Wp;
    As[0][akc+0][ar] = av.x; As[0][akc+1][ar] = av.y;
    As[0][akc+2][ar] = av.z; As[0][akc+3][ar] = av.w;
    *(float4*)&Bs[0][bkr][bc4] = bv;
    __syncthreads();

    int buf = 0;
    for (int k0 = 0; k0 < K; k0 += BK) {
        bool nxt = (k0 + BK) < K;
        if (nxt) {
            if (aval) {
                float4 a = *(const float4*)(Ap + k0 + BK);
                if (ASRC == 0) av = a;
                else {
                    float4 s = *(const float4*)(A2p + k0 + BK);
                    if (ASRC == 1) av = make_float4(a.x+s.x, a.y+s.y, a.z+s.z, a.w+s.w);
                    else           av = make_float4(a.x*s.x, a.y*s.y, a.z*s.z, a.w*s.w);
                }
            } else av = make_float4(0.f,0.f,0.f,0.f);
            bv = *(const float4*)(Wp + (size_t)(k0 + BK) * N);
        }
        #pragma unroll
        for (int kk = 0; kk < BK; kk++) {
            float4 a0 = *(const float4*)&As[buf][kk][ty * 4];
            float4 a1 = *(const float4*)&As[buf][kk][64 + ty * 4];
            float4 b0 = *(const float4*)&Bs[buf][kk][tx * 4];
            float4 b1 = *(const float4*)&Bs[buf][kk][64 + tx * 4];
            float a[8] = {a0.x,a0.y,a0.z,a0.w,a1.x,a1.y,a1.z,a1.w};
            float b[8] = {b0.x,b0.y,b0.z,b0.w,b1.x,b1.y,b1.z,b1.w};
            #pragma unroll
            for (int i = 0; i < 8; i++)
                #pragma unroll
                for (int j = 0; j < 8; j++)
                    acc[i][j] = fmaf(a[i], b[j], acc[i][j]);
        }
        if (nxt) {
            buf ^= 1;
            As[buf][akc+0][ar] = av.x; As[buf][akc+1][ar] = av.y;
            As[buf][akc+2][ar] = av.z; As[buf][akc+3][ar] = av.w;
            *(float4*)&Bs[buf][bkr][bc4] = bv;
            __syncthreads();
        }
    }

    // ---------------- epilogue ----------------
    int cA = col0 + tx * 4;
    int cB = col0 + 64 + tx * 4;
    float4 bias0 = *(const float4*)&bias[cA];
    float4 bias1 = *(const float4*)&bias[cB];
    float4 g0, g1, bb0, bb1;
    if (LNFUSE) {
        g0 = *(const float4*)&lng[cA]; g1 = *(const float4*)&lng[cB];
        bb0 = *(const float4*)&lnb[cA]; bb1 = *(const float4*)&lnb[cB];
    }

    #pragma unroll
    for (int i = 0; i < 8; i++) {
        int r = row0 + ((i < 4) ? (ty * 4 + i) : (64 + ty * 4 + (i - 4)));
        if (!LNFUSE && r >= M) continue;   // LN shapes are always divisible
        float v[8];
        v[0] = acc[i][0] + bias0.x; v[1] = acc[i][1] + bias0.y;
        v[2] = acc[i][2] + bias0.z; v[3] = acc[i][3] + bias0.w;
        v[4] = acc[i][4] + bias1.x; v[5] = acc[i][5] + bias1.y;
        v[6] = acc[i][6] + bias1.z; v[7] = acc[i][7] + bias1.w;
        if (HASRES) {
            float4 r0 = *(const float4*)&res[(size_t)r * N + cA];
            float4 r1 = *(const float4*)&res[(size_t)r * N + cB];
            v[0]+=r0.x; v[1]+=r0.y; v[2]+=r0.z; v[3]+=r0.w;
            v[4]+=r1.x; v[5]+=r1.y; v[6]+=r1.z; v[7]+=r1.w;
        }
        if (ACT == 1) {
            #pragma unroll
            for (int j = 0; j < 8; j++) v[j] = fmaxf(v[j], 0.f);
        } else if (ACT == 2) {
            #pragma unroll
            for (int j = 0; j < 8; j++) v[j] = (v[j] > 0.f) ? v[j] : 0.01f * v[j];
        }
        if (ACCUM) {
            float4 c0 = *(const float4*)&C[(size_t)r * N + cA];
            float4 c1 = *(const float4*)&C[(size_t)r * N + cB];
            v[0]+=c0.x; v[1]+=c0.y; v[2]+=c0.z; v[3]+=c0.w;
            v[4]+=c1.x; v[5]+=c1.y; v[6]+=c1.z; v[7]+=c1.w;
        }
        if (LNFUSE) {
            float s = 0.f, sq = 0.f;
            #pragma unroll
            for (int j = 0; j < 8; j++) { s += v[j]; sq += v[j] * v[j]; }
            #pragma unroll
            for (int off = 8; off >= 1; off >>= 1) {
                s  += __shfl_xor_sync(0xFFFFFFFFu, s,  off);
                sq += __shfl_xor_sync(0xFFFFFFFFu, sq, off);
            }
            float mean = s * (1.f / 128.f);
            float var  = sq * (1.f / 128.f) - mean * mean;
            float rs = rsqrtf(var + 1e-5f);
            v[0] = (v[0]-mean)*rs*g0.x + bb0.x; v[1] = (v[1]-mean)*rs*g0.y + bb0.y;
            v[2] = (v[2]-mean)*rs*g0.z + bb0.z; v[3] = (v[3]-mean)*rs*g0.w + bb0.w;
            v[4] = (v[4]-mean)*rs*g1.x + bb1.x; v[5] = (v[5]-mean)*rs*g1.y + bb1.y;
            v[6] = (v[6]-mean)*rs*g1.z + bb1.z; v[7] = (v[7]-mean)*rs*g1.w + bb1.w;
        }
        *(float4*)&C[(size_t)r * N + cA] = make_float4(v[0], v[1], v[2], v[3]);
        *(float4*)&C[(size_t)r * N + cB] = make_float4(v[4], v[5], v[6], v[7]);
    }
}

// ---------------- fused attention (per (batch, head) block, online softmax) --------
__global__ __launch_bounds__(LSEQ) void attn_kernel(
    const float* __restrict__ q, const float* __restrict__ k,
    const float* __restrict__ v, float* __restrict__ o)
{
    __shared__ float Ks[LSEQ][DK];
    __shared__ float Vs[LSEQ][DK];
    int b = blockIdx.x / NHEAD;
    int h = blockIdx.x % NHEAD;
    int t = threadIdx.x;

    size_t base = ((size_t)b * LSEQ + t) * D + h * DK;
    {
        const float4* kp = (const float4*)(k + base);
        const float4* vp = (const float4*)(v + base);
        float4* ksd = (float4*)Ks[t];
        float4* vsd = (float4*)Vs[t];
        #pragma unroll
        for (int i = 0; i < 4; i++) { ksd[i] = kp[i]; vsd[i] = vp[i]; }
    }
    __syncthreads();

    float qr[DK];
    {
        const float4* qp = (const float4*)(q + base);
        #pragma unroll
        for (int i = 0; i < 4; i++) {
            float4 qq = qp[i];
            qr[i*4+0] = qq.x; qr[i*4+1] = qq.y; qr[i*4+2] = qq.z; qr[i*4+3] = qq.w;
        }
    }

    float mx = -1e30f, sm = 0.f;
    float oacc[DK] = {};
    for (int m = 0; m < LSEQ; m++) {
        float s = 0.f;
        #pragma unroll
        for (int d = 0; d < DK; d++) s = fmaf(qr[d], Ks[m][d], s);
        s *= 0.25f;
        float nm = fmaxf(mx, s);
        float corr = __expf(mx - nm);
        float p    = __expf(s  - nm);
        sm = sm * corr + p;
        #pragma unroll
        for (int d = 0; d < DK; d++) oacc[d] = fmaf(oacc[d], corr, p * Vs[m][d]);
        mx = nm;
    }
    float inv = 1.f / sm;
    float4* op = (float4*)(o + base);
    #pragma unroll
    for (int i = 0; i < 4; i++)
        op[i] = make_float4(oacc[i*4+0]*inv, oacc[i*4+1]*inv, oacc[i*4+2]*inv, oacc[i*4+3]*inv);
}

// ---------------- host launch ----------------
extern "C" void kernel_launch(void* const* d_in, const int* in_sizes, int n_in,
                              void* d_out, int out_size)
{
    const float* ego    = (const float*)d_in[0];
    const float* vals   = (const float*)d_in[1];
    const float* W1     = (const float*)d_in[2];
    const float* b1     = (const float*)d_in[3];
    const float* W2     = (const float*)d_in[4];
    const float* b2     = (const float*)d_in[5];
    const float* enc_in = (const float*)d_in[6];
    const float* wq     = (const float*)d_in[7];
    const float* bq     = (const float*)d_in[8];
    const float* wk     = (const float*)d_in[9];
    const float* bk     = (const float*)d_in[10];
    const float* wv     = (const float*)d_in[11];
    const float* bv     = (const float*)d_in[12];
    const float* wo     = (const float*)d_in[13];
    const float* bo     = (const float*)d_in[14];
    const float* ln1_g  = (const float*)d_in[15];
    const float* ln1_b  = (const float*)d_in[16];
    const float* cw1    = (const float*)d_in[17];
    const float* cb1    = (const float*)d_in[18];
    const float* cw2    = (const float*)d_in[19];
    const float* cb2    = (const float*)d_in[20];
    const float* ln2_g  = (const float*)d_in[21];
    const float* ln2_b  = (const float*)d_in[22];
    const int*   rows   = (const int*)d_in[23];
    const int*   cols   = (const int*)d_in[24];

    int N   = in_sizes[0] / D;
    int nnz = in_sizes[1];

    float* agg_out = (float*)d_out;
    float* x_out   = (float*)d_out + (size_t)N * D;

    float *side, *x, *q, *kk, *vv, *o, *hh;
    cudaGetSymbolAddress((void**)&side, g_side);
    cudaGetSymbolAddress((void**)&x,    g_x);
    cudaGetSymbolAddress((void**)&q,    g_q);
    cudaGetSymbolAddress((void**)&kk,   g_k);
    cudaGetSymbolAddress((void**)&vv,   g_v);
    cudaGetSymbolAddress((void**)&o,    g_o);
    cudaGetSymbolAddress((void**)&hh,   g_h);

    // ---- stage 1: SpMM + bi-interaction (sum/prod fused into GEMM A-loaders) ----
    int n4 = (N * D) / 4;
    zero_kernel<<<(n4 + 255) / 256, 256>>>(side, n4);
    spmm_kernel<<<(nnz + EPB - 1) / EPB, D>>>(vals, rows, cols, ego, side, nnz);

    dim3 gagg(1, (N + BM - 1) / BM);
    gemm_tpl<1, 2, false, false, false><<<gagg, 256>>>(
        ego, side, W1, b1, nullptr, nullptr, nullptr, agg_out, N, D, D);
    gemm_tpl<2, 2, true, false, false><<<gagg, 256>>>(
        ego, side, W2, b2, nullptr, nullptr, nullptr, agg_out, N, D, D);

    // ---- stage 2: transformer encoder ----
    dim3 g1(1, NTOK / BM);       // N=128 GEMMs
    dim3 g2(DI / BN, NTOK / BM); // N=512 GEMM
    for (int i = 0; i < NLAYER; i++) {
        const float* xin = (i == 0) ? enc_in : x;
        const float* wq_i  = wq  + (size_t)i * D * D;
        const float* wk_i  = wk  + (size_t)i * D * D;
        const float* wv_i  = wv  + (size_t)i * D * D;
        const float* wo_i  = wo  + (size_t)i * D * D;
        const float* cw1_i = cw1 + (size_t)i * D * DI;
        const float* cw2_i = cw2 + (size_t)i * DI * D;

        gemm_tpl<0, 0, false, false, false><<<g1, 256>>>(
            xin, nullptr, wq_i, bq + i * D, nullptr, nullptr, nullptr, q, NTOK, D, D);
        gemm_tpl<0, 0, false, false, false><<<g1, 256>>>(
            xin, nullptr, wk_i, bk + i * D, nullptr, nullptr, nullptr, kk, NTOK, D, D);
        gemm_tpl<0, 0, false, false, false><<<g1, 256>>>(
            xin, nullptr, wv_i, bv + i * D, nullptr, nullptr, nullptr, vv, NTOK, D, D);

        attn_kernel<<<BT * NHEAD, LSEQ>>>(q, kk, vv, o);

        // t = o@wo + bo + x ; x = LN1(t)   (fused)
        gemm_tpl<0, 0, false, true, true><<<g1, 256>>>(
            o, nullptr, wo_i, bo + i * D, xin, ln1_g + i * D, ln1_b + i * D, x, NTOK, D, D);

        // h = relu(x@cw1 + cb1)
        gemm_tpl<0, 1, false, false, false><<<g2, 256>>>(
            x, nullptr, cw1_i, cb1 + i * DI, nullptr, nullptr, nullptr, hh, NTOK, DI, D);

        // out = LN2(h@cw2 + cb2 + x)   (fused)
        float* outp = (i == NLAYER - 1) ? x_out : x;
        gemm_tpl<0, 0, false, true, true><<<g1, 256>>>(
            hh, nullptr, cw2_i, cb2 + i * D, x, ln2_g + i * D, ln2_b + i * D, outp, NTOK, D, DI);
    }
}

// round 3
// speedup vs baseline: 1.2319x; 1.2319x over previous
#include <cuda_runtime.h>
#include <math.h>
#include <stdint.h>

// Problem constants (fixed by the dataset)
#define D      128
#define BT     32
#define LSEQ   256
#define NTOK   (BT*LSEQ)     // 8192
#define NHEAD  8
#define DK     16
#define DI     512
#define NMAX   100000
#define NLAYER 2

// ---------------- scratch (device globals) ----------------
__device__ float g_side[(size_t)NMAX * D];
__device__ float g_x[(size_t)NTOK * D];
__device__ float g_q[(size_t)NTOK * D];
__device__ float g_k[(size_t)NTOK * D];
__device__ float g_v[(size_t)NTOK * D];
__device__ float g_o[(size_t)NTOK * D];
__device__ float g_t[(size_t)NTOK * D];
__device__ float g_h[(size_t)NTOK * DI];

// ---------------- utility kernels ----------------
__global__ void zero_kernel(float* __restrict__ p, int n4) {
    int i = blockIdx.x * blockDim.x + threadIdx.x;
    if (i < n4) ((float4*)p)[i] = make_float4(0.f, 0.f, 0.f, 0.f);
}

// ---------------- sorted-COO SpMM with run-length accumulation ----------------
#define EPB 256
__global__ __launch_bounds__(D) void spmm_kernel(
    const float* __restrict__ vals, const int* __restrict__ rows,
    const int* __restrict__ cols, const float* __restrict__ ego,
    float* __restrict__ side, int nnz)
{
    __shared__ int   s_row[EPB];
    __shared__ int   s_col[EPB];
    __shared__ float s_val[EPB];
    int e0 = blockIdx.x * EPB;
    int cnt = min(EPB, nnz - e0);
    if (cnt <= 0) return;
    for (int i = threadIdx.x; i < cnt; i += blockDim.x) {
        s_row[i] = rows[e0 + i];
        s_col[i] = cols[e0 + i];
        s_val[i] = vals[e0 + i];
    }
    __syncthreads();
    int t = threadIdx.x;
    float acc = 0.f;
    int cur = s_row[0];
    for (int i = 0; i < cnt; i++) {
        int r = s_row[i];
        if (r != cur) {
            atomicAdd(&side[(size_t)cur * D + t], acc);
            acc = 0.f;
            cur = r;
        }
        acc = fmaf(s_val[i], __ldg(&ego[(size_t)s_col[i] * D + t]), acc);
    }
    atomicAdd(&side[(size_t)cur * D + t], acc);
}

// ---------------- tf32x3 tensor-core GEMM ----------------
// C[M,N] = epi(Aop[M,K] @ W[K,N]); Aop: A (ASRC=0), A+A2 (1), A*A2 (2)
// Epilogue: +bias, +res (HASRES), ACT (0 none, 1 relu, 2 leaky 0.01), +=C (ACCUM)
// Block tile 64x128, 8 warps (2m x 4n), warp tile 32x32 via m16n8k8.
#define GBM 64
#define GBN 128
#define GBK 16
#define ASTR 72      // As [k][m], (8k+m)%32 conflict-free fragment reads
#define BSTR 136     // Bs [k][n], (8k+n)%32 conflict-free fragment reads

__device__ __forceinline__ uint32_t f2tf(float f) {
    uint32_t u;
    asm("cvt.rna.tf32.f32 %0, %1;" : "=r"(u) : "f"(f));
    return u;
}

__device__ __forceinline__ void mma8(float* c, const uint32_t* a, const uint32_t* b) {
    asm volatile(
        "mma.sync.aligned.m16n8k8.row.col.f32.tf32.tf32.f32 "
        "{%0,%1,%2,%3}, {%4,%5,%6,%7}, {%8,%9}, {%0,%1,%2,%3};"
        : "+f"(c[0]), "+f"(c[1]), "+f"(c[2]), "+f"(c[3])
        : "r"(a[0]), "r"(a[1]), "r"(a[2]), "r"(a[3]), "r"(b[0]), "r"(b[1]));
}

template<int ASRC, int ACT, bool ACCUM, bool HASRES>
__global__ __launch_bounds__(256, 2) void gemm_tc(
    const float* __restrict__ A, const float* __restrict__ A2,
    const float* __restrict__ W, const float* __restrict__ bias,
    const float* __restrict__ res, float* __restrict__ C,
    int M, int N, int K)
{
    __shared__ float As[2][GBK][ASTR];
    __shared__ float Bs[2][GBK][BSTR];

    const int tid  = threadIdx.x;
    const int wid  = tid >> 5;
    const int lane = tid & 31;
    const int wm   = (wid >> 2) * 32;   // 0 / 32
    const int wn   = (wid & 3) * 32;    // 0..96
    const int row0 = blockIdx.y * GBM;
    const int col0 = blockIdx.x * GBN;

    // A loader: thread -> (m row, k quad)
    const int al_m = tid >> 2;          // 0..63
    const int al_k = (tid & 3) * 4;     // 0,4,8,12
    const int grow = row0 + al_m;
    const bool aval = grow < M;
    const float* Ap  = A + (size_t)grow * K + al_k;
    const float* A2p = (ASRC ? A2 : A) + (size_t)grow * K + al_k;

    // B loader: thread -> (k row, n oct)
    const int bl_k = tid >> 4;          // 0..15
    const int bl_n = (tid & 15) * 8;    // 0..120
    const float* Wp = W + (size_t)bl_k * N + col0 + bl_n;

    float acc[2][4][4] = {};

    auto load_stage = [&](int k0, int buf) {
        float4 a = make_float4(0.f, 0.f, 0.f, 0.f);
        if (aval) {
            a = *(const float4*)(Ap + k0);
            if (ASRC) {
                float4 s = *(const float4*)(A2p + k0);
                if (ASRC == 1) a = make_float4(a.x+s.x, a.y+s.y, a.z+s.z, a.w+s.w);
                else           a = make_float4(a.x*s.x, a.y*s.y, a.z*s.z, a.w*s.w);
            }
        }
        As[buf][al_k+0][al_m] = a.x;
        As[buf][al_k+1][al_m] = a.y;
        As[buf][al_k+2][al_m] = a.z;
        As[buf][al_k+3][al_m] = a.w;
        const float* wp = Wp + (size_t)k0 * N;
        *(float4*)&Bs[buf][bl_k][bl_n]     = *(const float4*)(wp);
        *(float4*)&Bs[buf][bl_k][bl_n + 4] = *(const float4*)(wp + 4);
    };

    load_stage(0, 0);
    __syncthreads();

    const int nstages = K / GBK;
    for (int s = 0; s < nstages; s++) {
        int buf = s & 1;
        if (s + 1 < nstages) load_stage((s + 1) * GBK, buf ^ 1);

        #pragma unroll
        for (int half = 0; half < 2; half++) {
            const int kk = half * 8;
            uint32_t ahi[2][4], alo[2][4], bhi[4][2], blo[4][2];
            #pragma unroll
            for (int mi = 0; mi < 2; mi++) {
                int r = wm + mi * 16 + (lane >> 2);
                int c = kk + (lane & 3);
                float a0 = As[buf][c][r];
                float a1 = As[buf][c][r + 8];
                float a2 = As[buf][c + 4][r];
                float a3 = As[buf][c + 4][r + 8];
                ahi[mi][0] = f2tf(a0); alo[mi][0] = f2tf(a0 - __uint_as_float(ahi[mi][0]));
                ahi[mi][1] = f2tf(a1); alo[mi][1] = f2tf(a1 - __uint_as_float(ahi[mi][1]));
                ahi[mi][2] = f2tf(a2); alo[mi][2] = f2tf(a2 - __uint_as_float(ahi[mi][2]));
                ahi[mi][3] = f2tf(a3); alo[mi][3] = f2tf(a3 - __uint_as_float(ahi[mi][3]));
            }
            #pragma unroll
            for (int ni = 0; ni < 4; ni++) {
                int n = wn + ni * 8 + (lane >> 2);
                float b0 = Bs[buf][kk + (lane & 3)][n];
                float b1 = Bs[buf][kk + 4 + (lane & 3)][n];
                bhi[ni][0] = f2tf(b0); blo[ni][0] = f2tf(b0 - __uint_as_float(bhi[ni][0]));
                bhi[ni][1] = f2tf(b1); blo[ni][1] = f2tf(b1 - __uint_as_float(bhi[ni][1]));
            }
            #pragma unroll
            for (int mi = 0; mi < 2; mi++)
                #pragma unroll
                for (int ni = 0; ni < 4; ni++)
                    mma8(acc[mi][ni], ahi[mi], bhi[ni]);
            #pragma unroll
            for (int mi = 0; mi < 2; mi++)
                #pragma unroll
                for (int ni = 0; ni < 4; ni++)
                    mma8(acc[mi][ni], alo[mi], bhi[ni]);
            #pragma unroll
            for (int mi = 0; mi < 2; mi++)
                #pragma unroll
                for (int ni = 0; ni < 4; ni++)
                    mma8(acc[mi][ni], ahi[mi], blo[ni]);
        }
        __syncthreads();
    }

    // ---------------- epilogue ----------------
    #pragma unroll
    for (int mi = 0; mi < 2; mi++) {
        #pragma unroll
        for (int ni = 0; ni < 4; ni++) {
            int c = col0 + wn + ni * 8 + 2 * (lane & 3);
            float bi0 = bias[c], bi1 = bias[c + 1];
            #pragma unroll
            for (int half = 0; half < 2; half++) {
                int r = row0 + wm + mi * 16 + (lane >> 2) + half * 8;
                if (r >= M) continue;
                float v0 = acc[mi][ni][half * 2 + 0] + bi0;
                float v1 = acc[mi][ni][half * 2 + 1] + bi1;
                if (HASRES) {
                    float2 rr = *(const float2*)&res[(size_t)r * N + c];
                    v0 += rr.x; v1 += rr.y;
                }
                if (ACT == 1) { v0 = fmaxf(v0, 0.f); v1 = fmaxf(v1, 0.f); }
                else if (ACT == 2) {
                    v0 = (v0 > 0.f) ? v0 : 0.01f * v0;
                    v1 = (v1 > 0.f) ? v1 : 0.01f * v1;
                }
                if (ACCUM) {
                    float2 cc = *(const float2*)&C[(size_t)r * N + c];
                    v0 += cc.x; v1 += cc.y;
                }
                *(float2*)&C[(size_t)r * N + c] = make_float2(v0, v1);
            }
        }
    }
}

// ---------------- fused attention (per (batch, head) block, online softmax) -------
__global__ __launch_bounds__(LSEQ) void attn_kernel(
    const float* __restrict__ q, const float* __restrict__ k,
    const float* __restrict__ v, float* __restrict__ o)
{
    __shared__ float Ks[LSEQ][DK];
    __shared__ float Vs[LSEQ][DK];
    int b = blockIdx.x / NHEAD;
    int h = blockIdx.x % NHEAD;
    int t = threadIdx.x;

    size_t base = ((size_t)b * LSEQ + t) * D + h * DK;
    {
        const float4* kp = (const float4*)(k + base);
        const float4* vp = (const float4*)(v + base);
        float4* ksd = (float4*)Ks[t];
        float4* vsd = (float4*)Vs[t];
        #pragma unroll
        for (int i = 0; i < 4; i++) { ksd[i] = kp[i]; vsd[i] = vp[i]; }
    }
    __syncthreads();

    float qr[DK];
    {
        const float4* qp = (const float4*)(q + base);
        #pragma unroll
        for (int i = 0; i < 4; i++) {
            float4 qq = qp[i];
            qr[i*4+0] = qq.x; qr[i*4+1] = qq.y; qr[i*4+2] = qq.z; qr[i*4+3] = qq.w;
        }
    }

    float mx = -1e30f, sm = 0.f;
    float oacc[DK] = {};
    for (int m = 0; m < LSEQ; m++) {
        float s = 0.f;
        #pragma unroll
        for (int d = 0; d < DK; d++) s = fmaf(qr[d], Ks[m][d], s);
        s *= 0.25f;
        float nm = fmaxf(mx, s);
        float corr = __expf(mx - nm);
        float p    = __expf(s  - nm);
        sm = sm * corr + p;
        #pragma unroll
        for (int d = 0; d < DK; d++) oacc[d] = fmaf(oacc[d], corr, p * Vs[m][d]);
        mx = nm;
    }
    float inv = 1.f / sm;
    float4* op = (float4*)(o + base);
    #pragma unroll
    for (int i = 0; i < 4; i++)
        op[i] = make_float4(oacc[i*4+0]*inv, oacc[i*4+1]*inv, oacc[i*4+2]*inv, oacc[i*4+3]*inv);
}

// ---------------- LayerNorm (one warp per row of 128) ----------------
__global__ __launch_bounds__(32) void ln_kernel(
    const float* __restrict__ in, const float* __restrict__ g,
    const float* __restrict__ b, float* __restrict__ out)
{
    int row = blockIdx.x;
    int lane = threadIdx.x;
    const float4* p = (const float4*)(in + (size_t)row * D);
    float4 x = p[lane];
    float s  = x.x + x.y + x.z + x.w;
    float sq = x.x*x.x + x.y*x.y + x.z*x.z + x.w*x.w;
    #pragma unroll
    for (int off = 16; off; off >>= 1) {
        s  += __shfl_xor_sync(0xFFFFFFFFu, s,  off);
        sq += __shfl_xor_sync(0xFFFFFFFFu, sq, off);
    }
    float mean = s * (1.f / D);
    float var  = sq * (1.f / D) - mean * mean;
    float rs = rsqrtf(var + 1e-5f);
    float4 gg = ((const float4*)g)[lane];
    float4 bb = ((const float4*)b)[lane];
    float4 r;
    r.x = (x.x - mean) * rs * gg.x + bb.x;
    r.y = (x.y - mean) * rs * gg.y + bb.y;
    r.z = (x.z - mean) * rs * gg.z + bb.z;
    r.w = (x.w - mean) * rs * gg.w + bb.w;
    ((float4*)(out + (size_t)row * D))[lane] = r;
}

// ---------------- host launch ----------------
extern "C" void kernel_launch(void* const* d_in, const int* in_sizes, int n_in,
                              void* d_out, int out_size)
{
    const float* ego    = (const float*)d_in[0];
    const float* vals   = (const float*)d_in[1];
    const float* W1     = (const float*)d_in[2];
    const float* b1     = (const float*)d_in[3];
    const float* W2     = (const float*)d_in[4];
    const float* b2     = (const float*)d_in[5];
    const float* enc_in = (const float*)d_in[6];
    const float* wq     = (const float*)d_in[7];
    const float* bq     = (const float*)d_in[8];
    const float* wk     = (const float*)d_in[9];
    const float* bk     = (const float*)d_in[10];
    const float* wv     = (const float*)d_in[11];
    const float* bv     = (const float*)d_in[12];
    const float* wo     = (const float*)d_in[13];
    const float* bo     = (const float*)d_in[14];
    const float* ln1_g  = (const float*)d_in[15];
    const float* ln1_b  = (const float*)d_in[16];
    const float* cw1    = (const float*)d_in[17];
    const float* cb1    = (const float*)d_in[18];
    const float* cw2    = (const float*)d_in[19];
    const float* cb2    = (const float*)d_in[20];
    const float* ln2_g  = (const float*)d_in[21];
    const float* ln2_b  = (const float*)d_in[22];
    const int*   rows   = (const int*)d_in[23];
    const int*   cols   = (const int*)d_in[24];

    int N   = in_sizes[0] / D;
    int nnz = in_sizes[1];

    float* agg_out = (float*)d_out;
    float* x_out   = (float*)d_out + (size_t)N * D;

    float *side, *x, *q, *kk, *vv, *o, *t, *hh;
    cudaGetSymbolAddress((void**)&side, g_side);
    cudaGetSymbolAddress((void**)&x,    g_x);
    cudaGetSymbolAddress((void**)&q,    g_q);
    cudaGetSymbolAddress((void**)&kk,   g_k);
    cudaGetSymbolAddress((void**)&vv,   g_v);
    cudaGetSymbolAddress((void**)&o,    g_o);
    cudaGetSymbolAddress((void**)&t,    g_t);
    cudaGetSymbolAddress((void**)&hh,   g_h);

    // ---- stage 1: SpMM + bi-interaction ----
    int n4 = (N * D) / 4;
    zero_kernel<<<(n4 + 255) / 256, 256>>>(side, n4);
    spmm_kernel<<<(nnz + EPB - 1) / EPB, D>>>(vals, rows, cols, ego, side, nnz);

    dim3 gagg(1, (N + GBM - 1) / GBM);
    gemm_tc<1, 2, false, false><<<gagg, 256>>>(ego, side, W1, b1, nullptr, agg_out, N, D, D);
    gemm_tc<2, 2, true,  false><<<gagg, 256>>>(ego, side, W2, b2, nullptr, agg_out, N, D, D);

    // ---- stage 2: transformer encoder ----
    dim3 g1(1, NTOK / GBM);        // N=128 GEMMs: 128 blocks
    dim3 g2(DI / GBN, NTOK / GBM); // N=512 GEMM: 512 blocks
    for (int i = 0; i < NLAYER; i++) {
        const float* xin = (i == 0) ? enc_in : x;
        const float* wq_i  = wq  + (size_t)i * D * D;
        const float* wk_i  = wk  + (size_t)i * D * D;
        const float* wv_i  = wv  + (size_t)i * D * D;
        const float* wo_i  = wo  + (size_t)i * D * D;
        const float* cw1_i = cw1 + (size_t)i * D * DI;
        const float* cw2_i = cw2 + (size_t)i * DI * D;

        gemm_tc<0, 0, false, false><<<g1, 256>>>(xin, nullptr, wq_i, bq + i * D, nullptr, q,  NTOK, D, D);
        gemm_tc<0, 0, false, false><<<g1, 256>>>(xin, nullptr, wk_i, bk + i * D, nullptr, kk, NTOK, D, D);
        gemm_tc<0, 0, false, false><<<g1, 256>>>(xin, nullptr, wv_i, bv + i * D, nullptr, vv, NTOK, D, D);

        attn_kernel<<<BT * NHEAD, LSEQ>>>(q, kk, vv, o);

        // t = o@wo + bo + xin ; x = LN1(t)
        gemm_tc<0, 0, false, true><<<g1, 256>>>(o, nullptr, wo_i, bo + i * D, xin, t, NTOK, D, D);
        ln_kernel<<<NTOK, 32>>>(t, ln1_g + i * D, ln1_b + i * D, x);

        // h = relu(x@cw1 + cb1)
        gemm_tc<0, 1, false, false><<<g2, 256>>>(x, nullptr, cw1_i, cb1 + i * DI, nullptr, hh, NTOK, DI, D);

        // t = h@cw2 + cb2 + x ; out = LN2(t)
        gemm_tc<0, 0, false, true><<<g1, 256>>>(hh, nullptr, cw2_i, cb2 + i * D, x, t, NTOK, D, DI);
        float* outp = (i == NLAYER - 1) ? x_out : x;
        ln_kernel<<<NTOK, 32>>>(t, ln2_g + i * D, ln2_b + i * D, outp);
    }
}